// round 14
// baseline (speedup 1.0000x reference)
#include <cuda_runtime.h>
#include <cuda_fp16.h>
#include <math.h>

typedef unsigned int u32;

#define DID 4096
#define EXP 64
#define NE 128          // 64 clean + 64 noise output columns
#define MT 64           // rows per CTA
#define KC 64           // k per chunk
#define NCH (DID / KC)  // 64 chunks
#define THREADS 256
#define INV_SC (1.0f / 134217728.0f)   // 2^-27: qA0(2^5)*qB1(2^22) == qA1(2^17)*qB0(2^10)

// ---------------- global scratch ----------------
__device__ unsigned short g_w0[NE][DID];    // fp16 main limb of weights [n][k]
__device__ signed char    g_qb0[NE][DID];   // int8 w * 2^10
__device__ signed char    g_qb1[NE][DID];   // int8 (w - fp16(w)) * 2^22
__device__ float g_importance[EXP];
__device__ int   g_load[EXP];
__device__ int   g_count;

// ---------------- smem layout (97.3KB/CTA -> 2 CTAs/SM) ----------------
// [0,16K)   A0 fp16: buf(2) x 8KB   [64r][128B] swizzled
// [16K,24K) qA0 s8:  buf(2) x 4KB   [64r][64B]  macro-row layout
// [24K,32K) qA1 s8:  buf(2) x 4KB
// [32K,96K) B: stage(2) x { B0 fp16 16KB, qB0 8KB, qB1 8KB }
// [96K,+1K) control;  logits overlay [64][132] f32 = 33.8KB reuses [0,34K)
#define A0_OFF(b)  ((b) * 8192)
#define QA0_OFF(b) (16384 + (b) * 4096)
#define QA1_OFF(b) (24576 + (b) * 4096)
#define B0_OFF(s)  (32768 + (s) * 32768)
#define QB0_OFF(s) (32768 + (s) * 32768 + 16384)
#define QB1_OFF(s) (32768 + (s) * 32768 + 24576)
#define CTRL_OFF   98304
#define SMEM_BYTES (98304 + 1024)
#define LSTRIDE    132

// macro-row addressing for 64B-row int8 tiles (4x 16B units/row), conflict-free ldsm
__device__ __forceinline__ u32 tile_addr64(int row, int unit) {
    return (u32)(((row >> 1) * 128) + ((((unit) + ((row & 1) << 2)) ^ ((row >> 1) & 3)) << 4));
}

// ---------------- PTX helpers ----------------
__device__ __forceinline__ u32 smem_u32(const void* p) {
    u32 a;
    asm("{ .reg .u64 t; cvta.to.shared.u64 t, %1; cvt.u32.u64 %0, t; }" : "=r"(a) : "l"(p));
    return a;
}
__device__ __forceinline__ void cp16(u32 dst, const void* src) {
    asm volatile("cp.async.cg.shared.global [%0], [%1], 16;" :: "r"(dst), "l"(src));
}
#define CP_COMMIT() asm volatile("cp.async.commit_group;")
#define CP_WAIT0()  asm volatile("cp.async.wait_group 0;")

__device__ __forceinline__ void ldsm4(u32 addr, u32& r0, u32& r1, u32& r2, u32& r3) {
    asm volatile("ldmatrix.sync.aligned.m8n8.x4.shared.b16 {%0,%1,%2,%3}, [%4];"
                 : "=r"(r0), "=r"(r1), "=r"(r2), "=r"(r3) : "r"(addr));
}
// fp32-accumulate HMMA (main term)
__device__ __forceinline__ void mma_f32(float* d, const u32* a, const u32* b) {
    asm volatile("mma.sync.aligned.m16n8k16.row.col.f32.f16.f16.f32 "
                 "{%0,%1,%2,%3}, {%4,%5,%6,%7}, {%8,%9}, {%0,%1,%2,%3};"
                 : "+f"(d[0]), "+f"(d[1]), "+f"(d[2]), "+f"(d[3])
                 : "r"(a[0]), "r"(a[1]), "r"(a[2]), "r"(a[3]), "r"(b[0]), "r"(b[1]));
}
// int8 IMMA k32, exact s32 accumulate (merged cross terms)
__device__ __forceinline__ void mma_s8(int* d, const u32* a, const u32* b) {
    asm volatile("mma.sync.aligned.m16n8k32.row.col.s32.s8.s8.s32 "
                 "{%0,%1,%2,%3}, {%4,%5,%6,%7}, {%8,%9}, {%0,%1,%2,%3};"
                 : "+r"(d[0]), "+r"(d[1]), "+r"(d[2]), "+r"(d[3])
                 : "r"(a[0]), "r"(a[1]), "r"(a[2]), "r"(a[3]), "r"(b[0]), "r"(b[1]));
}

__device__ __forceinline__ u32 pack_s8x4(int x0, int x1, int x2, int x3) {
    u32 t, d;
    asm("cvt.pack.sat.s8.s32.b32 %0, %1, %2, 0;" : "=r"(t) : "r"(x3), "r"(x2));
    asm("cvt.pack.sat.s8.s32.b32 %0, %1, %2, %3;" : "=r"(d) : "r"(x1), "r"(x0), "r"(t));
    return d;  // bytes [b0=x0, b1=x1, b2=x2, b3=x3]
}

__device__ __forceinline__ float softplus_f(float z) {
    return (z > 0.0f) ? (z + log1pf(expf(-z))) : log1pf(expf(z));
}

// ---------------- weight pre-split kernel ----------------
__global__ void __launch_bounds__(256) split_w_kernel(const float* __restrict__ gw,
                                                      const float* __restrict__ wn) {
    __shared__ float t[64][65];
    int k0 = blockIdx.x * 64;
    for (int half = 0; half < 2; half++) {
        const float* src = half ? wn : gw;
        __syncthreads();
        for (int i = threadIdx.x; i < 64 * 64; i += 256) {
            int kk = i >> 6, n = i & 63;
            t[n][kk] = src[(size_t)(k0 + kk) * EXP + n];
        }
        __syncthreads();
        for (int i = threadIdx.x; i < 64 * 16; i += 256) {
            int n = i >> 4, c = i & 15;
            int nn = half * 64 + n;
            unsigned short h0[4];
            int q0[4], q1[4];
            #pragma unroll
            for (int j = 0; j < 4; j++) {
                float v = t[n][c * 4 + j];
                __half h = __float2half_rn(v);
                float rw = v - __half2float(h);
                h0[j] = __half_as_ushort(h);
                q0[j] = __float2int_rn(v * 1024.0f);
                q1[j] = __float2int_rn(rw * 4194304.0f);   // 2^22
            }
            *(uint2*)&g_w0[nn][k0 + c * 4] =
                make_uint2((u32)h0[0] | ((u32)h0[1] << 16), (u32)h0[2] | ((u32)h0[3] << 16));
            *(u32*)&g_qb0[nn][k0 + c * 4] = pack_s8x4(q0[0], q0[1], q0[2], q0[3]);
            *(u32*)&g_qb1[nn][k0 + c * 4] = pack_s8x4(q1[0], q1[1], q1[2], q1[3]);
        }
    }
}

// ---------------- main router kernel ----------------
__global__ void __launch_bounds__(THREADS, 2)
router_kernel(const float* __restrict__ x,
              const float* __restrict__ gate_b,
              const float* __restrict__ noise,
              float* __restrict__ out, int B, int nblocks)
{
    extern __shared__ __align__(1024) char smc[];
    const u32 sb = smem_u32(smc);
    float* bias_s  = (float*)(smc + CTRL_OFF);
    float* imp_s   = (float*)(smc + CTRL_OFF + 256);
    int*   load_s  = (int*)(smc + CTRL_OFF + 512);
    int*   is_last = (int*)(smc + CTRL_OFF + 768);

    const int tid = threadIdx.x;
    const int wid = tid >> 5, lane = tid & 31;
    const int m0 = blockIdx.x * MT;
    const int mwarp = wid & 1;        // 2 row groups of 32
    const int nwarp = wid >> 1;       // 4 col groups of 32

    if (tid < EXP) { bias_s[tid] = gate_b[tid]; imp_s[tid] = 0.0f; load_s[tid] = 0; }

    float accM[2][4][4];   // fp32 main accumulator
    int   accC[2][4][4];   // s32 merged cross accumulator (scale 2^27)
    #pragma unroll
    for (int mt = 0; mt < 2; mt++)
        #pragma unroll
        for (int nt = 0; nt < 4; nt++)
            #pragma unroll
            for (int r = 0; r < 4; r++) { accM[mt][nt][r] = 0.0f; accC[mt][nt][r] = 0; }

    // ldmatrix lane constants
    const int a_row = lane & 15;
    const int a_kb  = lane >> 4;
    const int b_row = (lane & 7) + ((lane >> 4) & 1) * 8;
    const int b_kb  = (lane >> 3) & 1;

    // x/convert mapping: u = tid + i*256 -> row = u>>4 (0..63), c = u&15 (float4 col)
    int xrow[4], xc[4];
    u32 asw[4], qsw[4];
    #pragma unroll
    for (int i = 0; i < 4; i++) {
        int u = tid + i * 256;
        xrow[i] = u >> 4; xc[i] = u & 15;
        asw[i] = (u32)(xrow[i] * 128 + (((xc[i] >> 1) ^ (xrow[i] & 7)) * 16) + (xc[i] & 1) * 8);
        qsw[i] = tile_addr64(xrow[i], xc[i] >> 2) + (u32)((xc[i] & 3) * 4);
    }
    // B0 fp16 cp mapping: u = tid + i*256 (i<4): n = u>>3, cu = u&7
    // qB cp mapping:      u = tid + i*256 (i<2): n = u>>2, cu = u&3

    float4 xr[4];

    // convert helper lambda-ish macro: writes A0, qA0, qA1 for this thread's 4 float4
    #define CONVERT_X(buf) do {                                                   \
        _Pragma("unroll")                                                         \
        for (int i = 0; i < 4; i++) {                                             \
            float4 v = xr[i];                                                     \
            __half2 h0a = __floats2half2_rn(v.x, v.y);                            \
            __half2 h0b = __floats2half2_rn(v.z, v.w);                            \
            float2 f0a = __half22float2(h0a);                                     \
            float2 f0b = __half22float2(h0b);                                     \
            *(uint2*)(smc + A0_OFF(buf) + asw[i]) =                               \
                make_uint2(*(u32*)&h0a, *(u32*)&h0b);                             \
            int p0 = __float2int_rn(v.x * 32.0f), p1 = __float2int_rn(v.y * 32.0f); \
            int p2 = __float2int_rn(v.z * 32.0f), p3 = __float2int_rn(v.w * 32.0f); \
            *(u32*)(smc + QA0_OFF(buf) + qsw[i]) = pack_s8x4(p0, p1, p2, p3);     \
            int r0 = __float2int_rn((v.x - f0a.x) * 131072.0f);                   \
            int r1 = __float2int_rn((v.y - f0a.y) * 131072.0f);                   \
            int r2 = __float2int_rn((v.z - f0b.x) * 131072.0f);                   \
            int r3 = __float2int_rn((v.w - f0b.y) * 131072.0f);                   \
            *(u32*)(smc + QA1_OFF(buf) + qsw[i]) = pack_s8x4(r0, r1, r2, r3);     \
        }                                                                         \
    } while (0)

    #define CP_B(stage, k0v) do {                                                 \
        _Pragma("unroll")                                                         \
        for (int i = 0; i < 4; i++) {                                             \
            int u = tid + i * 256;                                                \
            int n = u >> 3, cu = u & 7;                                           \
            u32 sw = (u32)(n * 128 + ((cu ^ (n & 7)) * 16));                      \
            cp16(sb + B0_OFF(stage) + sw, &g_w0[n][(k0v) + cu * 8]);              \
        }                                                                         \
        _Pragma("unroll")                                                         \
        for (int i = 0; i < 2; i++) {                                             \
            int u = tid + i * 256;                                                \
            int n = u >> 2, cu = u & 3;                                           \
            u32 sw = tile_addr64(n, cu);                                          \
            cp16(sb + QB0_OFF(stage) + sw, &g_qb0[n][(k0v) + cu * 16]);           \
            cp16(sb + QB1_OFF(stage) + sw, &g_qb1[n][(k0v) + cu * 16]);           \
        }                                                                         \
    } while (0)

    // ---- prologue ----
    {
        #pragma unroll
        for (int i = 0; i < 4; i++)
            xr[i] = *(const float4*)(x + (size_t)(m0 + xrow[i]) * DID + xc[i] * 4);
        CP_B(0, 0);
        CP_COMMIT();
        CONVERT_X(0);
        #pragma unroll
        for (int i = 0; i < 4; i++)
            xr[i] = *(const float4*)(x + (size_t)(m0 + xrow[i]) * DID + KC + xc[i] * 4);
        CP_WAIT0();
        __syncthreads();
    }

    #pragma unroll 1
    for (int kc = 0; kc < NCH; kc++) {
        const int ab = kc & 1;

        if (kc + 1 < NCH) CP_B(ab ^ 1, (kc + 1) * KC);
        CP_COMMIT();

        if (kc + 1 < NCH) CONVERT_X(ab ^ 1);

        if (kc + 2 < NCH) {
            const int k0n = (kc + 2) * KC;
            #pragma unroll
            for (int i = 0; i < 4; i++)
                xr[i] = *(const float4*)(x + (size_t)(m0 + xrow[i]) * DID + k0n + xc[i] * 4);
        }

        // ---- main GEMM (fp16, f32 acc): 4 k16 steps ----
        const u32 a0b = sb + A0_OFF(ab), b0b = sb + B0_OFF(ab);
        #pragma unroll
        for (int ks = 0; ks < 4; ks++) {
            u32 A0[2][4];
            #pragma unroll
            for (int mt = 0; mt < 2; mt++) {
                int row = mwarp * 32 + mt * 16 + a_row;
                u32 off = (u32)(row * 128 + (((ks * 2 + a_kb) ^ (row & 7)) * 16));
                ldsm4(a0b + off, A0[mt][0], A0[mt][1], A0[mt][2], A0[mt][3]);
            }
            u32 B0[4][2];
            #pragma unroll
            for (int p = 0; p < 2; p++) {
                int n = nwarp * 32 + p * 16 + b_row;
                u32 off = (u32)(n * 128 + (((ks * 2 + b_kb) ^ (n & 7)) * 16));
                u32 r0, r1, r2, r3;
                ldsm4(b0b + off, r0, r1, r2, r3);
                B0[p * 2][0] = r0; B0[p * 2][1] = r1; B0[p * 2 + 1][0] = r2; B0[p * 2 + 1][1] = r3;
            }
            #pragma unroll
            for (int mt = 0; mt < 2; mt++)
                #pragma unroll
                for (int nt = 0; nt < 4; nt++)
                    mma_f32(accM[mt][nt], A0[mt], B0[nt]);
        }

        // ---- cross GEMMs (int8 k32, s32 acc): 2 k32 steps ----
        const u32 qa0b = sb + QA0_OFF(ab), qa1b = sb + QA1_OFF(ab);
        const u32 qb0b = sb + QB0_OFF(ab), qb1b = sb + QB1_OFF(ab);
        #pragma unroll
        for (int kq = 0; kq < 2; kq++) {
            u32 Aq0[2][4], Aq1[2][4];
            #pragma unroll
            for (int mt = 0; mt < 2; mt++) {
                int row = mwarp * 32 + mt * 16 + a_row;
                u32 off = tile_addr64(row, kq * 2 + a_kb);
                ldsm4(qa0b + off, Aq0[mt][0], Aq0[mt][1], Aq0[mt][2], Aq0[mt][3]);
                ldsm4(qa1b + off, Aq1[mt][0], Aq1[mt][1], Aq1[mt][2], Aq1[mt][3]);
            }
            u32 Bq0[4][2], Bq1[4][2];
            #pragma unroll
            for (int p = 0; p < 2; p++) {
                int n = nwarp * 32 + p * 16 + b_row;
                u32 off = tile_addr64(n, kq * 2 + b_kb);
                u32 r0, r1, r2, r3;
                ldsm4(qb0b + off, r0, r1, r2, r3);
                Bq0[p * 2][0] = r0; Bq0[p * 2][1] = r1; Bq0[p * 2 + 1][0] = r2; Bq0[p * 2 + 1][1] = r3;
                ldsm4(qb1b + off, r0, r1, r2, r3);
                Bq1[p * 2][0] = r0; Bq1[p * 2][1] = r1; Bq1[p * 2 + 1][0] = r2; Bq1[p * 2 + 1][1] = r3;
            }
            #pragma unroll
            for (int mt = 0; mt < 2; mt++)
                #pragma unroll
                for (int nt = 0; nt < 4; nt++) {
                    mma_s8(accC[mt][nt], Aq0[mt], Bq1[nt]);   // A0 * B1
                    mma_s8(accC[mt][nt], Aq1[mt], Bq0[nt]);   // A1 * B0
                }
        }

        CP_WAIT0();        // B(kc+1) fully landed (issued a chunk earlier; ~free)
        __syncthreads();
    }

    // ---- write combined logits to smem overlay [64][LSTRIDE] ----
    float* lsm = (float*)smc;
    {
        const int gid = lane >> 2, tig = lane & 3;
        #pragma unroll
        for (int mt = 0; mt < 2; mt++)
            #pragma unroll
            for (int nt = 0; nt < 4; nt++) {
                int r0 = mwarp * 32 + mt * 16 + gid;
                int cc = nwarp * 32 + nt * 8 + tig * 2;
                float f0 = fmaf((float)accC[mt][nt][0], INV_SC, accM[mt][nt][0]);
                float f1 = fmaf((float)accC[mt][nt][1], INV_SC, accM[mt][nt][1]);
                float f2 = fmaf((float)accC[mt][nt][2], INV_SC, accM[mt][nt][2]);
                float f3 = fmaf((float)accC[mt][nt][3], INV_SC, accM[mt][nt][3]);
                *(float2*)&lsm[r0 * LSTRIDE + cc]       = make_float2(f0, f1);
                *(float2*)&lsm[(r0 + 8) * LSTRIDE + cc] = make_float2(f2, f3);
            }
    }
    __syncthreads();

    // ---- epilogue: warps 0-1, one row per lane ----
    if (wid < 2) {
        const int rloc = wid * 32 + lane;
        const int row = m0 + rloc;
        const float* nrow = noise + (size_t)row * EXP;
        float l[64];
        #pragma unroll
        for (int e = 0; e < 64; e += 4) {
            float4 cl = *(const float4*)&lsm[rloc * LSTRIDE + e];
            float4 nl = *(const float4*)&lsm[rloc * LSTRIDE + 64 + e];
            float4 nz = *(const float4*)(nrow + e);
            l[e + 0] = fmaf(nz.x, softplus_f(nl.x), cl.x + bias_s[e + 0]);
            l[e + 1] = fmaf(nz.y, softplus_f(nl.y), cl.y + bias_s[e + 1]);
            l[e + 2] = fmaf(nz.z, softplus_f(nl.z), cl.z + bias_s[e + 2]);
            l[e + 3] = fmaf(nz.w, softplus_f(nl.w), cl.w + bias_s[e + 3]);
        }

        // top-2, lowest index wins ties (matches jax.lax.top_k)
        float v1 = -INFINITY, v2 = -INFINITY;
        int i1 = -1, i2 = -1;
        #pragma unroll
        for (int e = 0; e < 64; e++) {
            float le = l[e];
            if (le > v1) { v2 = v1; i2 = i1; v1 = le; i1 = e; }
            else if (le > v2) { v2 = le; i2 = e; }
        }

        // full softmax for importance
        float esum = 0.0f;
        #pragma unroll
        for (int e = 0; e < 64; e++) { l[e] = expf(l[e] - v1); esum += l[e]; }
        float inv = 1.0f / esum;

        #pragma unroll
        for (int e = 0; e < 64; e++) {
            float p = l[e] * inv;
            p += __shfl_xor_sync(0xffffffffu, p, 16);
            p += __shfl_xor_sync(0xffffffffu, p, 8);
            p += __shfl_xor_sync(0xffffffffu, p, 4);
            p += __shfl_xor_sync(0xffffffffu, p, 2);
            p += __shfl_xor_sync(0xffffffffu, p, 1);
            if (lane == 0) atomicAdd(&imp_s[e], p);
        }

        float e21 = expf(v2 - v1);
        float g1 = 1.0f / (1.0f + e21);
        float g2 = e21 * g1;
        *(float2*)(out + (size_t)row * 2) = make_float2(g1, g2);
        *(float2*)(out + (size_t)B * 2 + (size_t)row * 2) = make_float2((float)i1, (float)i2);
        atomicAdd(&load_s[i1], 1);
        atomicAdd(&load_s[i2], 1);
    }
    __syncthreads();

    if (tid < EXP) {
        atomicAdd(&g_importance[tid], imp_s[tid]);
        atomicAdd(&g_load[tid], load_s[tid]);
    }

    // last CTA: finalize aux loss + reset globals for the next graph replay
    __threadfence();
    if (tid == 0) {
        int c = atomicAdd(&g_count, 1);
        *is_last = (c == nblocks - 1) ? 1 : 0;
    }
    __syncthreads();
    if (*is_last) {
        if (tid < EXP) imp_s[tid] = g_importance[tid] * (float)g_load[tid];
        __syncthreads();
        if (tid == 0) {
            float tot = 0.0f;
            #pragma unroll
            for (int i = 0; i < EXP; i++) tot += imp_s[i];
            out[(size_t)B * 4] = tot * (float)EXP;   // mean * E^2 = sum * E
            g_count = 0;
        }
        if (tid < EXP) { g_importance[tid] = 0.0f; g_load[tid] = 0; }
    }
}

extern "C" void kernel_launch(void* const* d_in, const int* in_sizes, int n_in,
                              void* d_out, int out_size) {
    const float* x       = (const float*)d_in[0];
    const float* gate_w  = (const float*)d_in[1];
    const float* gate_b  = (const float*)d_in[2];
    const float* w_noise = (const float*)d_in[3];
    const float* noise   = (const float*)d_in[4];
    float* out = (float*)d_out;

    int B = in_sizes[0] / DID;
    int nblocks = B / MT;

    cudaFuncSetAttribute(router_kernel, cudaFuncAttributeMaxDynamicSharedMemorySize, SMEM_BYTES);

    split_w_kernel<<<DID / 64, 256>>>(gate_w, w_noise);
    router_kernel<<<nblocks, THREADS, SMEM_BYTES>>>(x, gate_b, noise, out, B, nblocks);
}

// round 15
// speedup vs baseline: 2.1939x; 2.1939x over previous
#include <cuda_runtime.h>
#include <cuda_fp16.h>
#include <math.h>

typedef unsigned int u32;

#define DID 4096
#define EXP 64
#define NE 128          // 64 clean + 64 noise output columns
#define MT 64           // rows per CTA
#define KC 64           // k per chunk
#define NCH (DID / KC)  // 64 chunks
#define THREADS 128
#define RSCALE 4096.0f
#define INV_RSCALE (1.0f / 4096.0f)

// ---------------- global scratch ----------------
__device__ unsigned short g_w0[NE][DID];   // fp16 main limb of weights [n][k]
__device__ unsigned short g_w1[NE][DID];   // fp16 residual limb (pre-scaled by 4096)
__device__ float g_importance[EXP];
__device__ int   g_load[EXP];
__device__ int   g_count;

// ---------------- smem layout (97.3KB/CTA -> 2 CTAs/SM) ----------------
// [0,32K)   A fp16 limb tiles: buf(2) x limb(2) x 8KB  [64r][128B] swizzled
// [32K,96K) B fp16 limb tiles: stage(2) x limb(2) x 16KB [128n][128B] swizzled
// [96K,+1K) control;  logits overlay [64][132] f32 = 33.8KB reuses [0,34K)
#define A_OFF(b, l) ((b) * 16384 + (l) * 8192)
#define B_OFF(s, l) (32768 + (s) * 32768 + (l) * 16384)
#define CTRL_OFF    98304
#define SMEM_BYTES  (98304 + 1024)
#define LSTRIDE     132

// ---------------- PTX helpers ----------------
__device__ __forceinline__ u32 smem_u32(const void* p) {
    u32 a;
    asm("{ .reg .u64 t; cvta.to.shared.u64 t, %1; cvt.u32.u64 %0, t; }" : "=r"(a) : "l"(p));
    return a;
}
__device__ __forceinline__ void cp16(u32 dst, const void* src) {
    asm volatile("cp.async.cg.shared.global [%0], [%1], 16;" :: "r"(dst), "l"(src));
}
#define CP_COMMIT() asm volatile("cp.async.commit_group;")
#define CP_WAIT0()  asm volatile("cp.async.wait_group 0;")

__device__ __forceinline__ void ldsm4(u32 addr, u32& r0, u32& r1, u32& r2, u32& r3) {
    asm volatile("ldmatrix.sync.aligned.m8n8.x4.shared.b16 {%0,%1,%2,%3}, [%4];"
                 : "=r"(r0), "=r"(r1), "=r"(r2), "=r"(r3) : "r"(addr));
}
// fp32-accumulate HMMA (main term)
__device__ __forceinline__ void mma_f32(float* d, const u32* a, const u32* b) {
    asm volatile("mma.sync.aligned.m16n8k16.row.col.f32.f16.f16.f32 "
                 "{%0,%1,%2,%3}, {%4,%5,%6,%7}, {%8,%9}, {%0,%1,%2,%3};"
                 : "+f"(d[0]), "+f"(d[1]), "+f"(d[2]), "+f"(d[3])
                 : "r"(a[0]), "r"(a[1]), "r"(a[2]), "r"(a[3]), "r"(b[0]), "r"(b[1]));
}
// fp16-accumulate HMMA (cross terms; folded by /4096 in epilogue)
__device__ __forceinline__ void mma_f16(u32* d, const u32* a, const u32* b) {
    asm volatile("mma.sync.aligned.m16n8k16.row.col.f16.f16.f16.f16 "
                 "{%0,%1}, {%2,%3,%4,%5}, {%6,%7}, {%0,%1};"
                 : "+r"(d[0]), "+r"(d[1])
                 : "r"(a[0]), "r"(a[1]), "r"(a[2]), "r"(a[3]), "r"(b[0]), "r"(b[1]));
}

// scalar split (weight pre-split kernel only)
__device__ __forceinline__ void split2(float v, unsigned short& h0, unsigned short& h1) {
    __half a = __float2half_rn(v);
    float r = (v - __half2float(a)) * RSCALE;
    __half b = __float2half_rn(r);
    h0 = __half_as_ushort(a);
    h1 = __half_as_ushort(b);
}

// vector split: float4 -> (h0 pair-packed uint2, h1 pair-packed uint2)
__device__ __forceinline__ void split2v(float4 v, uint2& m, uint2& r) {
    __half2 h0a = __floats2half2_rn(v.x, v.y);
    __half2 h0b = __floats2half2_rn(v.z, v.w);
    float2 f0a = __half22float2(h0a);
    float2 f0b = __half22float2(h0b);
    __half2 h1a = __floats2half2_rn((v.x - f0a.x) * RSCALE, (v.y - f0a.y) * RSCALE);
    __half2 h1b = __floats2half2_rn((v.z - f0b.x) * RSCALE, (v.w - f0b.y) * RSCALE);
    m.x = *(u32*)&h0a; m.y = *(u32*)&h0b;
    r.x = *(u32*)&h1a; r.y = *(u32*)&h1b;
}

__device__ __forceinline__ float softplus_f(float z) {
    return (z > 0.0f) ? (z + log1pf(expf(-z))) : log1pf(expf(z));
}

// ---------------- weight pre-split kernel ----------------
__global__ void __launch_bounds__(256) split_w_kernel(const float* __restrict__ gw,
                                                      const float* __restrict__ wn) {
    __shared__ float t[64][65];
    int k0 = blockIdx.x * 64;
    for (int half = 0; half < 2; half++) {
        const float* src = half ? wn : gw;
        __syncthreads();
        for (int i = threadIdx.x; i < 64 * 64; i += 256) {
            int kk = i >> 6, n = i & 63;
            t[n][kk] = src[(size_t)(k0 + kk) * EXP + n];
        }
        __syncthreads();
        for (int i = threadIdx.x; i < 64 * 16; i += 256) {
            int n = i >> 4, c = i & 15;
            int nn = half * 64 + n;
            unsigned short h0[4], h1[4];
            #pragma unroll
            for (int j = 0; j < 4; j++) split2(t[n][c * 4 + j], h0[j], h1[j]);
            *(uint2*)&g_w0[nn][k0 + c * 4] =
                make_uint2((u32)h0[0] | ((u32)h0[1] << 16), (u32)h0[2] | ((u32)h0[3] << 16));
            *(uint2*)&g_w1[nn][k0 + c * 4] =
                make_uint2((u32)h1[0] | ((u32)h1[1] << 16), (u32)h1[2] | ((u32)h1[3] << 16));
        }
    }
}

// ---------------- main router kernel ----------------
// 4 warps. warp wid covers cols wid*32..+32 over ALL 64 rows (warp tile 64x32).
// mt 0..3 = 16-row frags, nt 0..3 = 8-col frags.
__global__ void __launch_bounds__(THREADS, 2)
router_kernel(const float* __restrict__ x,
              const float* __restrict__ gate_b,
              const float* __restrict__ noise,
              float* __restrict__ out, int B, int nblocks)
{
    extern __shared__ __align__(1024) char smc[];
    const u32 sb = smem_u32(smc);
    float* bias_s  = (float*)(smc + CTRL_OFF);
    float* imp_s   = (float*)(smc + CTRL_OFF + 256);
    int*   load_s  = (int*)(smc + CTRL_OFF + 512);
    int*   is_last = (int*)(smc + CTRL_OFF + 768);

    const int tid = threadIdx.x;
    const int wid = tid >> 5, lane = tid & 31;
    const int m0 = blockIdx.x * MT;
    const int nwarp = wid;            // 4 col groups of 32

    if (tid < EXP) { bias_s[tid] = gate_b[tid]; imp_s[tid] = 0.0f; load_s[tid] = 0; }

    float accM[4][4][4];   // fp32 main accumulator (64 regs)
    u32   accC[4][4][2];   // fp16x2 cross accumulator (32 regs)
    #pragma unroll
    for (int mt = 0; mt < 4; mt++)
        #pragma unroll
        for (int nt = 0; nt < 4; nt++) {
            #pragma unroll
            for (int r = 0; r < 4; r++) accM[mt][nt][r] = 0.0f;
            accC[mt][nt][0] = 0u; accC[mt][nt][1] = 0u;
        }

    // fragment registers (pass-1 operands double-buffered across ks)
    u32 A0f[2][16], B0f[2][4][2];
    u32 A1f[16],    B1f[4][2];

    // ldmatrix lane constants
    const int a_row = lane & 15;
    const int a_kb  = lane >> 4;
    const int b_row = (lane & 7) + ((lane >> 4) & 1) * 8;
    const int b_kb  = (lane >> 3) & 1;

    float4 xr[4];   // one x wave (4 float4)

    // ---- helpers ----
    auto LDG_WAVE = [&](int w, int k0v) {
        #pragma unroll
        for (int i = 0; i < 4; i++) {
            int u = (w * 4 + i) * 128 + tid;
            int row = u >> 4, c = u & 15;
            xr[i] = *(const float4*)(x + (size_t)(m0 + row) * DID + k0v + c * 4);
        }
    };
    auto CONVERT_WAVE = [&](int w, int dstbuf) {
        #pragma unroll
        for (int i = 0; i < 4; i++) {
            int u = (w * 4 + i) * 128 + tid;
            int row = u >> 4, c = u & 15;
            u32 off = (u32)(row * 128 + (((c >> 1) ^ (row & 7)) * 16) + (c & 1) * 8);
            uint2 m, r;
            split2v(xr[i], m, r);
            *(uint2*)(smc + A_OFF(dstbuf, 0) + off) = m;
            *(uint2*)(smc + A_OFF(dstbuf, 1) + off) = r;
        }
    };
    auto CP_B = [&](int st, int k0v) {
        #pragma unroll
        for (int i = 0; i < 8; i++) {
            int u = i * 128 + tid;
            int n = u >> 3, cu = u & 7;
            u32 sw = (u32)(n * 128 + ((cu ^ (n & 7)) * 16));
            cp16(sb + B_OFF(st, 0) + sw, &g_w0[n][k0v + cu * 8]);
            cp16(sb + B_OFF(st, 1) + sw, &g_w1[n][k0v + cu * 8]);
        }
    };

    // ---- prologue ----
    {
        LDG_WAVE(0, 0);
        CP_B(0, 0);
        CP_COMMIT();
        CONVERT_WAVE(0, 0);
        LDG_WAVE(1, 0);
        CONVERT_WAVE(1, 0);
        LDG_WAVE(0, KC);      // wave0 of chunk 1 (consumed at ks0 of chunk 0)
        CP_WAIT0();
        __syncthreads();
    }

    #pragma unroll 1
    for (int kc = 0; kc < NCH; kc++) {
        const int ab = kc & 1;

        if (kc + 1 < NCH) CP_B(ab ^ 1, (kc + 1) * KC);
        CP_COMMIT();

        const u32 a0b = sb + A_OFF(ab, 0), a1b = sb + A_OFF(ab, 1);
        const u32 b0b = sb + B_OFF(ab, 0), b1b = sb + B_OFF(ab, 1);

        auto LOAD_A0B0 = [&](u32* Af, u32 (*Bf)[2], int ksv) {
            #pragma unroll
            for (int mt = 0; mt < 4; mt++) {
                int row = mt * 16 + a_row;
                u32 off = (u32)(row * 128 + (((ksv * 2 + a_kb) ^ (row & 7)) * 16));
                ldsm4(a0b + off, Af[mt * 4], Af[mt * 4 + 1], Af[mt * 4 + 2], Af[mt * 4 + 3]);
            }
            #pragma unroll
            for (int p = 0; p < 2; p++) {
                int n = nwarp * 32 + p * 16 + b_row;
                u32 off = (u32)(n * 128 + (((ksv * 2 + b_kb) ^ (n & 7)) * 16));
                ldsm4(b0b + off, Bf[p * 2][0], Bf[p * 2][1], Bf[p * 2 + 1][0], Bf[p * 2 + 1][1]);
            }
        };
        auto LOAD_A1B1 = [&](int ksv) {
            #pragma unroll
            for (int mt = 0; mt < 4; mt++) {
                int row = mt * 16 + a_row;
                u32 off = (u32)(row * 128 + (((ksv * 2 + a_kb) ^ (row & 7)) * 16));
                ldsm4(a1b + off, A1f[mt * 4], A1f[mt * 4 + 1], A1f[mt * 4 + 2], A1f[mt * 4 + 3]);
            }
            #pragma unroll
            for (int p = 0; p < 2; p++) {
                int n = nwarp * 32 + p * 16 + b_row;
                u32 off = (u32)(n * 128 + (((ksv * 2 + b_kb) ^ (n & 7)) * 16));
                ldsm4(b1b + off, B1f[p * 2][0], B1f[p * 2][1], B1f[p * 2 + 1][0], B1f[p * 2 + 1][1]);
            }
        };

        LOAD_A0B0(A0f[0], B0f[0], 0);

        #pragma unroll
        for (int ks = 0; ks < 4; ks++) {
            const int cur = ks & 1;
            if (ks < 3) LOAD_A0B0(A0f[cur ^ 1], B0f[cur ^ 1], ks + 1);   // prefetch next ks
            LOAD_A1B1(ks);                                               // used >=16 MMAs later

            // pass 1: main GEMM, f32 acc
            #pragma unroll
            for (int mt = 0; mt < 4; mt++)
                #pragma unroll
                for (int nt = 0; nt < 4; nt++)
                    mma_f32(accM[mt][nt], &A0f[cur][mt * 4], B0f[cur][nt]);
            // pass 2: A0 * B1 (f16 acc)
            #pragma unroll
            for (int mt = 0; mt < 4; mt++)
                #pragma unroll
                for (int nt = 0; nt < 4; nt++)
                    mma_f16(accC[mt][nt], &A0f[cur][mt * 4], B1f[nt]);
            // pass 3: A1 * B0 (f16 acc)
            #pragma unroll
            for (int mt = 0; mt < 4; mt++)
                #pragma unroll
                for (int nt = 0; nt < 4; nt++)
                    mma_f16(accC[mt][nt], A1f + mt * 4, B0f[cur][nt]);

            // staged x pipeline (issues while tensor drains the MMA backlog)
            if (ks == 0 && kc + 1 < NCH) { CONVERT_WAVE(0, ab ^ 1); LDG_WAVE(1, (kc + 1) * KC); }
            if (ks == 2 && kc + 1 < NCH) { CONVERT_WAVE(1, ab ^ 1); }
            if (ks == 3 && kc + 2 < NCH) { LDG_WAVE(0, (kc + 2) * KC); }
        }

        CP_WAIT0();
        __syncthreads();
    }

    // ---- write combined logits to smem overlay [64][LSTRIDE] ----
    float* lsm = (float*)smc;
    {
        const int gid = lane >> 2, tig = lane & 3;
        #pragma unroll
        for (int mt = 0; mt < 4; mt++)
            #pragma unroll
            for (int nt = 0; nt < 4; nt++) {
                int r0 = mt * 16 + gid;
                int cc = nwarp * 32 + nt * 8 + tig * 2;
                float2 c0 = __half22float2(*(__half2*)&accC[mt][nt][0]);
                float2 c1 = __half22float2(*(__half2*)&accC[mt][nt][1]);
                float f0 = fmaf(c0.x, INV_RSCALE, accM[mt][nt][0]);
                float f1 = fmaf(c0.y, INV_RSCALE, accM[mt][nt][1]);
                float f2 = fmaf(c1.x, INV_RSCALE, accM[mt][nt][2]);
                float f3 = fmaf(c1.y, INV_RSCALE, accM[mt][nt][3]);
                *(float2*)&lsm[r0 * LSTRIDE + cc]       = make_float2(f0, f1);
                *(float2*)&lsm[(r0 + 8) * LSTRIDE + cc] = make_float2(f2, f3);
            }
    }
    __syncthreads();

    // ---- epilogue: warps 0-1, one row per lane ----
    if (wid < 2) {
        const int rloc = wid * 32 + lane;
        const int row = m0 + rloc;
        const float* nrow = noise + (size_t)row * EXP;
        float l[64];
        #pragma unroll
        for (int e = 0; e < 64; e += 4) {
            float4 cl = *(const float4*)&lsm[rloc * LSTRIDE + e];
            float4 nl = *(const float4*)&lsm[rloc * LSTRIDE + 64 + e];
            float4 nz = *(const float4*)(nrow + e);
            l[e + 0] = fmaf(nz.x, softplus_f(nl.x), cl.x + bias_s[e + 0]);
            l[e + 1] = fmaf(nz.y, softplus_f(nl.y), cl.y + bias_s[e + 1]);
            l[e + 2] = fmaf(nz.z, softplus_f(nl.z), cl.z + bias_s[e + 2]);
            l[e + 3] = fmaf(nz.w, softplus_f(nl.w), cl.w + bias_s[e + 3]);
        }

        // top-2, lowest index wins ties (matches jax.lax.top_k)
        float v1 = -INFINITY, v2 = -INFINITY;
        int i1 = -1, i2 = -1;
        #pragma unroll
        for (int e = 0; e < 64; e++) {
            float le = l[e];
            if (le > v1) { v2 = v1; i2 = i1; v1 = le; i1 = e; }
            else if (le > v2) { v2 = le; i2 = e; }
        }

        // full softmax for importance
        float esum = 0.0f;
        #pragma unroll
        for (int e = 0; e < 64; e++) { l[e] = expf(l[e] - v1); esum += l[e]; }
        float inv = 1.0f / esum;

        #pragma unroll
        for (int e = 0; e < 64; e++) {
            float p = l[e] * inv;
            p += __shfl_xor_sync(0xffffffffu, p, 16);
            p += __shfl_xor_sync(0xffffffffu, p, 8);
            p += __shfl_xor_sync(0xffffffffu, p, 4);
            p += __shfl_xor_sync(0xffffffffu, p, 2);
            p += __shfl_xor_sync(0xffffffffu, p, 1);
            if (lane == 0) atomicAdd(&imp_s[e], p);
        }

        float e21 = expf(v2 - v1);
        float g1 = 1.0f / (1.0f + e21);
        float g2 = e21 * g1;
        *(float2*)(out + (size_t)row * 2) = make_float2(g1, g2);
        *(float2*)(out + (size_t)B * 2 + (size_t)row * 2) = make_float2((float)i1, (float)i2);
        atomicAdd(&load_s[i1], 1);
        atomicAdd(&load_s[i2], 1);
    }
    __syncthreads();

    if (tid < EXP) {
        atomicAdd(&g_importance[tid], imp_s[tid]);
        atomicAdd(&g_load[tid], load_s[tid]);
    }

    // last CTA: finalize aux loss + reset globals for the next graph replay
    __threadfence();
    if (tid == 0) {
        int c = atomicAdd(&g_count, 1);
        *is_last = (c == nblocks - 1) ? 1 : 0;
    }
    __syncthreads();
    if (*is_last) {
        if (tid < EXP) imp_s[tid] = g_importance[tid] * (float)g_load[tid];
        __syncthreads();
        if (tid == 0) {
            float tot = 0.0f;
            #pragma unroll
            for (int i = 0; i < EXP; i++) tot += imp_s[i];
            out[(size_t)B * 4] = tot * (float)EXP;   // mean * E^2 = sum * E
            g_count = 0;
        }
        if (tid < EXP) { g_importance[tid] = 0.0f; g_load[tid] = 0; }
    }
}

extern "C" void kernel_launch(void* const* d_in, const int* in_sizes, int n_in,
                              void* d_out, int out_size) {
    const float* x       = (const float*)d_in[0];
    const float* gate_w  = (const float*)d_in[1];
    const float* gate_b  = (const float*)d_in[2];
    const float* w_noise = (const float*)d_in[3];
    const float* noise   = (const float*)d_in[4];
    float* out = (float*)d_out;

    int B = in_sizes[0] / DID;
    int nblocks = B / MT;

    cudaFuncSetAttribute(router_kernel, cudaFuncAttributeMaxDynamicSharedMemorySize, SMEM_BYTES);

    split_w_kernel<<<DID / 64, 256>>>(gate_w, w_noise);
    router_kernel<<<nblocks, THREADS, SMEM_BYTES>>>(x, gate_b, noise, out, B, nblocks);
}